// round 8
// baseline (speedup 1.0000x reference)
#include <cuda_runtime.h>
#include <math_constants.h>

// out = minmax_normalize( bicubic_up2x( LL[:, 0:8] ) )
// All other iqwt terms carry sum(gh)=sum(fl)=sum(fh)=0 (f32 residue < 3e-7);
// the surviving sg^2 scalar cancels in the min-max normalization.
//
// memset node: g_red sentinels (both 0xFFFFFFFF).
// Pass 1 (min/max) and Pass 2 (normalize+write) are linked by PDL:
// pass2 launches concurrently, overlaps its fill+horizontal with pass1, and
// griddepcontrol.wait's only before reading g_red for the epilogue.

#define THREADS 256
#define TILE_J  8             // input rows per block -> 16 output rows
#define IN_ROWS 12            // 8 + 4 halo
#define SMEM_W  264           // 4 pad | 256 | 4 pad
#define N_IN    256
#define N_OUT   512
#define N_IMG   64
#define TILES_PER_IMG 32
#define GRID (N_IMG * TILES_PER_IMG)   // 2048

// bicubic a=-0.75, src = 0.5*i - 0.25
#define WE0 (-0.03515625f)
#define WE1 ( 0.26171875f)
#define WE2 ( 0.87890625f)
#define WE3 (-0.10546875f)
#define WO0 (-0.10546875f)
#define WO1 ( 0.87890625f)
#define WO2 ( 0.26171875f)
#define WO3 (-0.03515625f)

__device__ unsigned int g_red[2];   // [0]=min(enc(v)), [1]=min(enc(-v))

__device__ __forceinline__ unsigned int encf(float f) {
    unsigned int u = __float_as_uint(f);
    return (u & 0x80000000u) ? ~u : (u | 0x80000000u);
}
__device__ __forceinline__ float decf(unsigned int e) {
    unsigned int u = (e & 0x80000000u) ? (e ^ 0x80000000u) : ~e;
    return __uint_as_float(u);
}

// ---- shared tile fill (input col c -> smem col c+4) -------------------------
__device__ __forceinline__ void fill_tile(float (*s)[SMEM_W],
                                          const float* __restrict__ src,
                                          int jbase, int t) {
#pragma unroll
    for (int i = 0; i < 3; i++) {
        const int f  = t + i * THREADS;      // 0..767
        const int rr = f >> 6;               // 0..11
        const int qc = f & 63;
        const int gr = min(max(jbase - 2 + rr, 0), N_IN - 1);
        *reinterpret_cast<float4*>(&s[rr][4 * qc + 4]) =
            *reinterpret_cast<const float4*>(src + gr * N_IN + 4 * qc);
    }
    if (t < IN_ROWS) {
        const int gr = min(max(jbase - 2 + t, 0), N_IN - 1);
        const float v = src[gr * N_IN];
        s[t][2] = v; s[t][3] = v;
    } else if (t >= 128 && t < 128 + IN_ROWS) {
        const int rr = t - 128;
        const int gr = min(max(jbase - 2 + rr, 0), N_IN - 1);
        const float v = src[gr * N_IN + (N_IN - 1)];
        s[rr][260] = v; s[rr][261] = v;
    }
}

// ---- horizontal pass into hb[8][4] ------------------------------------------
__device__ __forceinline__ void hpass(const float (*s)[SMEM_W], int k, int g,
                                      float hb[8][4]) {
#pragma unroll
    for (int r = 0; r < 8; r++) {
        const float* rp = &s[4 * g + r][2 * k + 2];
        const float2 z01 = *reinterpret_cast<const float2*>(rp);
        const float2 z23 = *reinterpret_cast<const float2*>(rp + 2);
        const float2 z45 = *reinterpret_cast<const float2*>(rp + 4);
        const float z0 = z01.x, z1 = z01.y, z2 = z23.x;
        const float z3 = z23.y, z4 = z45.x, z5 = z45.y;
        hb[r][0] = WE0 * z0 + WE1 * z1 + WE2 * z2 + WE3 * z3;
        hb[r][1] = WO0 * z1 + WO1 * z2 + WO2 * z3 + WO3 * z4;
        hb[r][2] = WE0 * z1 + WE1 * z2 + WE2 * z3 + WE3 * z4;
        hb[r][3] = WO0 * z2 + WO1 * z3 + WO2 * z4 + WO3 * z5;
    }
}

// ============================ pass 1: min/max ================================
__global__ __launch_bounds__(THREADS)
void qwt_minmax_kernel(const float* __restrict__ LL) {
    // Let the dependent (write) kernel start streaming immediately.
    asm volatile("griddepcontrol.launch_dependents;" ::: "memory");

    __shared__ __align__(16) float s[IN_ROWS][SMEM_W];
    const int t    = threadIdx.x;
    const int img  = blockIdx.x >> 5;
    const int tile = blockIdx.x & 31;
    const int b    = img >> 3;
    const int ch   = img & 7;
    const float* __restrict__ src = LL + (size_t)(b * 32 + ch) * (N_IN * N_IN);

    fill_tile(s, src, tile * TILE_J, t);
    __syncthreads();

    const int k = t & 127;
    const int g = t >> 7;
    float hb[8][4];
    hpass(s, k, g, hb);

    float lmin =  CUDART_INF_F;
    float lmax = -CUDART_INF_F;
#pragma unroll
    for (int a = 0; a < 8; a++) {
        const int ra = a >> 1;
        float o[4];
        if ((a & 1) == 0) {
#pragma unroll
            for (int c = 0; c < 4; c++)
                o[c] = WE0 * hb[ra][c] + WE1 * hb[ra + 1][c]
                     + WE2 * hb[ra + 2][c] + WE3 * hb[ra + 3][c];
        } else {
#pragma unroll
            for (int c = 0; c < 4; c++)
                o[c] = WO0 * hb[ra + 1][c] + WO1 * hb[ra + 2][c]
                     + WO2 * hb[ra + 3][c] + WO3 * hb[ra + 4][c];
        }
        lmin = fminf(lmin, fminf(fminf(o[0], o[1]), fminf(o[2], o[3])));
        lmax = fmaxf(lmax, fmaxf(fmaxf(o[0], o[1]), fmaxf(o[2], o[3])));
    }

#pragma unroll
    for (int off = 16; off > 0; off >>= 1) {
        lmin = fminf(lmin, __shfl_xor_sync(0xFFFFFFFFu, lmin, off));
        lmax = fmaxf(lmax, __shfl_xor_sync(0xFFFFFFFFu, lmax, off));
    }
    __shared__ float wmin[THREADS / 32], wmax[THREADS / 32];
    const int w = t >> 5, l = t & 31;
    if (l == 0) { wmin[w] = lmin; wmax[w] = lmax; }
    __syncthreads();
    if (t == 0) {
        float m = wmin[0], M = wmax[0];
#pragma unroll
        for (int i = 1; i < THREADS / 32; i++) {
            m = fminf(m, wmin[i]);
            M = fmaxf(M, wmax[i]);
        }
        atomicMin(&g_red[0], encf(m));
        atomicMin(&g_red[1], encf(-M));
    }
}

// ======================= pass 2: normalize + write ===========================
__global__ __launch_bounds__(THREADS)
void qwt_write_kernel(const float* __restrict__ LL, float* __restrict__ out) {
    __shared__ __align__(16) float s[IN_ROWS][SMEM_W];
    const int t    = threadIdx.x;
    const int img  = blockIdx.x >> 5;
    const int tile = blockIdx.x & 31;
    const int b    = img >> 3;
    const int ch   = img & 7;
    const float* __restrict__ src = LL + (size_t)(b * 32 + ch) * (N_IN * N_IN);

    fill_tile(s, src, tile * TILE_J, t);
    __syncthreads();

    const int k = t & 127;
    const int g = t >> 7;
    float hb[8][4];
    hpass(s, k, g, hb);

    // Block until pass 1 (and the memset before it) has fully completed and
    // flushed; only then is g_red valid.
    asm volatile("griddepcontrol.wait;" ::: "memory");
    const float mn =  decf(*(const volatile unsigned int*)&g_red[0]);
    const float mx = -decf(*(const volatile unsigned int*)&g_red[1]);
    const float scale = 1.0f / (mx - mn);
    const float bias  = -mn * scale;

    const size_t obase = (size_t)img * (N_OUT * N_OUT) + 4 * k;
    const int rbase = tile * 16 + 8 * g;
#pragma unroll
    for (int a = 0; a < 8; a++) {
        const int ra = a >> 1;
        float o[4];
        if ((a & 1) == 0) {
#pragma unroll
            for (int c = 0; c < 4; c++)
                o[c] = WE0 * hb[ra][c] + WE1 * hb[ra + 1][c]
                     + WE2 * hb[ra + 2][c] + WE3 * hb[ra + 3][c];
        } else {
#pragma unroll
            for (int c = 0; c < 4; c++)
                o[c] = WO0 * hb[ra + 1][c] + WO1 * hb[ra + 2][c]
                     + WO2 * hb[ra + 3][c] + WO3 * hb[ra + 4][c];
        }
        float4 v;
        v.x = fmaf(o[0], scale, bias); v.y = fmaf(o[1], scale, bias);
        v.z = fmaf(o[2], scale, bias); v.w = fmaf(o[3], scale, bias);
        *reinterpret_cast<float4*>(out + obase + (size_t)(rbase + a) * N_OUT) = v;
    }
}

extern "C" void kernel_launch(void* const* d_in, const int* in_sizes, int n_in,
                              void* d_out, int out_size) {
    const float* LL = (const float*)d_in[0];
    float* out = (float*)d_out;
    (void)in_sizes; (void)n_in; (void)out_size;

    static unsigned int* red_ptr = nullptr;
    if (!red_ptr) cudaGetSymbolAddress((void**)&red_ptr, g_red);

    cudaMemsetAsync(red_ptr, 0xFF, 2 * sizeof(unsigned int));
    qwt_minmax_kernel<<<GRID, THREADS>>>(LL);

    // PDL: write kernel launches while minmax runs; it self-synchronizes via
    // griddepcontrol.wait before consuming g_red.
    cudaLaunchConfig_t cfg = {};
    cfg.gridDim  = dim3(GRID);
    cfg.blockDim = dim3(THREADS);
    cudaLaunchAttribute attr[1];
    attr[0].id = cudaLaunchAttributeProgrammaticStreamSerialization;
    attr[0].val.programmaticStreamSerializationAllowed = 1;
    cfg.attrs = attr;
    cfg.numAttrs = 1;
    cudaLaunchKernelEx(&cfg, qwt_write_kernel, LL, out);
}